// round 2
// baseline (speedup 1.0000x reference)
#include <cuda_runtime.h>

// Problem dims (fixed by the dataset)
#define Bn 8
#define Cn 19
#define Hn 384
#define Wn 384
#define NPIX (Bn * Hn * Wn)
#define HWn (Hn * Wn)
#define BOUND 777  // B + C + H + W = 8+1+384+384

// Scratch (allocation-free rule: __device__ globals)
__device__ unsigned char  g_pred[NPIX];
__device__ unsigned short g_vert[NPIX];
__device__ float          g_ce;
__device__ unsigned int   g_border;

// ---------------------------------------------------------------------------
// Fast exp(x) for x <= 0 via FMA-pipe polynomial (avoids MUFU bottleneck).
// 2^f on f in [-0.5, 0.5] (Cephes minimax), exponent via bit trick.
// ---------------------------------------------------------------------------
__device__ __forceinline__ float fast_exp_neg(float x) {
    float t = x * 1.44269504088896341f;     // log2(e)
    t = fmaxf(t, -120.0f);                  // underflow clamp (result ~0)
    float n = rintf(t);
    float f = t - n;                        // [-0.5, 0.5]
    float p = 1.535336188319500e-4f;
    p = fmaf(p, f, 1.339887440266574e-3f);
    p = fmaf(p, f, 9.618437357674640e-3f);
    p = fmaf(p, f, 5.550332471162809e-2f);
    p = fmaf(p, f, 2.402264791363012e-1f);
    p = fmaf(p, f, 6.931472028550421e-1f);
    p = fmaf(p, f, 1.0f);
    int e = (int)n;                         // in [-120, 0]
    float sc = __int_as_float((e + 127) << 23);
    return p * sc;
}

// ---------------------------------------------------------------------------
// Kernel 0: zero the accumulators (graph replays must be idempotent).
// ---------------------------------------------------------------------------
__global__ void init_kernel() {
    g_ce = 0.0f;
    g_border = 0u;
}

// ---------------------------------------------------------------------------
// Kernel 1: fused cross-entropy (sum, ignore_index=255) + argmax (pred map).
// One thread per pixel; 19 channel values held in registers.
// ---------------------------------------------------------------------------
__global__ void __launch_bounds__(256) ce_argmax_kernel(
    const float* __restrict__ x, const int* __restrict__ tgt) {
    int idx = blockIdx.x * blockDim.x + threadIdx.x;
    float nll = 0.0f;
    if (idx < NPIX) {
        int b = idx / HWn;
        int hw = idx - b * HWn;
        const float* p = x + (size_t)b * Cn * HWn + hw;

        float v[Cn];
        #pragma unroll
        for (int c = 0; c < Cn; c++) v[c] = __ldg(p + (size_t)c * HWn);

        float m = v[0];
        int arg = 0;
        #pragma unroll
        for (int c = 1; c < Cn; c++) {
            if (v[c] > m) { m = v[c]; arg = c; }   // first-max tie break
        }
        g_pred[idx] = (unsigned char)arg;

        float s = 0.0f;
        #pragma unroll
        for (int c = 0; c < Cn; c++) s += fast_exp_neg(v[c] - m);

        int t = tgt[idx];
        if (t != 255) {
            // predicated select instead of dynamic register-array index
            float tv = v[0];
            #pragma unroll
            for (int c = 1; c < Cn; c++) tv = (c == t) ? v[c] : tv;
            float lse = m + __log2f(s) * 0.69314718055994531f;
            nll = lse - tv;
        }
    }
    // block reduction -> atomicAdd
    #pragma unroll
    for (int o = 16; o > 0; o >>= 1)
        nll += __shfl_down_sync(0xFFFFFFFFu, nll, o);
    __shared__ float ws[8];
    int lane = threadIdx.x & 31, wid = threadIdx.x >> 5;
    if (lane == 0) ws[wid] = nll;
    __syncthreads();
    if (wid == 0) {
        float v2 = (lane < (blockDim.x >> 5)) ? ws[lane] : 0.0f;
        #pragma unroll
        for (int o = 4; o > 0; o >>= 1)
            v2 += __shfl_down_sync(0xFFFFFFFFu, v2, o);
        if (lane == 0) atomicAdd(&g_ce, v2);
    }
}

// ---------------------------------------------------------------------------
// Kernel 2: target borders (computed on the fly) + vertical 1D chessboard DT.
// One thread per column; down pass then up pass. Result capped at BOUND.
// border(i,j) = ((t[i+1,j]-t[i,j]) + (t[i,j+1]-t[i,j])) != 0, zero-padded.
// ---------------------------------------------------------------------------
__global__ void __launch_bounds__(128) vert_dt_kernel(const int* __restrict__ tgt) {
    int j = blockIdx.x * blockDim.x + threadIdx.x;   // column 0..383
    int b = blockIdx.y;
    const int* tb = tgt + (size_t)b * HWn;
    unsigned short* gv = g_vert + (size_t)b * HWn;

    int cur  = tb[j];
    int curR = (j < Wn - 1) ? tb[j + 1] : cur;

    int v = BOUND;
    for (int i = 0; i < Hn; i++) {
        int nxt, nxtR;
        if (i < Hn - 1) {
            nxt  = tb[(i + 1) * Wn + j];
            nxtR = (j < Wn - 1) ? tb[(i + 1) * Wn + j + 1] : nxt;
        } else {
            nxt = cur; nxtR = curR;   // bottom row: tb diff padded to 0
        }
        int diff = (nxt - cur) + (curR - cur);
        int vp1 = v + 1; if (vp1 > BOUND) vp1 = BOUND;
        v = (diff != 0) ? 0 : vp1;
        gv[i * Wn + j] = (unsigned short)v;
        cur = nxt; curR = nxtR;
    }
    int u = BOUND;
    for (int i = Hn - 1; i >= 0; i--) {
        int gval = gv[i * Wn + j];
        int up1 = u + 1; if (up1 > BOUND) up1 = BOUND;
        u = min(gval, up1);
        gv[i * Wn + j] = (unsigned short)u;
    }
}

// ---------------------------------------------------------------------------
// Kernel 3: horizontal stage of Chebyshev DT via per-row sparse min-table +
// binary search, fused with pred-border masking and border-loss reduction.
// d(j) = min t : min_{|y-j|<=t} g(y) <= t   (monotone predicate).
// One block per (b, row), 384 threads.
// ---------------------------------------------------------------------------
__global__ void __launch_bounds__(Wn) horiz_dt_kernel() {
    __shared__ unsigned short T[9][Wn];   // sparse table, levels 0..8
    __shared__ int wsum[12];

    int row = blockIdx.x;           // 0 .. B*H-1
    int i = row % Hn;
    int j = threadIdx.x;
    int base = row * Wn;

    T[0][j] = g_vert[base + j];
    __syncthreads();

    #pragma unroll
    for (int k = 1; k <= 8; k++) {
        int h = 1 << (k - 1);
        int j2 = j + h;
        int lim = Wn - h;           // last valid index at level k-1
        if (j2 > lim) j2 = lim;
        unsigned short a = T[k - 1][j];
        unsigned short bv = T[k - 1][j2];
        unsigned short mn = a < bv ? a : bv;
        __syncthreads();
        T[k][j] = mn;
        __syncthreads();
    }

    // binary search for d(j) in [0, BOUND]
    int lo = 0, hi = BOUND;
    while (lo < hi) {
        int t = (lo + hi) >> 1;
        int a = j - t; if (a < 0) a = 0;
        int bb = j + t; if (bb > Wn - 1) bb = Wn - 1;
        int L = bb - a + 1;
        int k = 31 - __clz(L);
        int q1 = T[k][a];
        int q2 = T[k][bb - (1 << k) + 1];
        int q = q1 < q2 ? q1 : q2;
        if (q <= t) hi = t; else lo = t + 1;
    }
    int d = lo;

    // pred border at (b, i, j)
    int pidx = base + j;            // == b*HWn + i*Wn + j
    int p0 = g_pred[pidx];
    int pd = (i < Hn - 1) ? (int)g_pred[pidx + Wn] : p0;
    int pr = (j < Wn - 1) ? (int)g_pred[pidx + 1]  : p0;
    int contrib = (((pd - p0) + (pr - p0)) != 0) ? d : 0;

    // integer block reduction (exact) -> u32 atomic
    #pragma unroll
    for (int o = 16; o > 0; o >>= 1)
        contrib += __shfl_down_sync(0xFFFFFFFFu, contrib, o);
    int lane = threadIdx.x & 31, wid = threadIdx.x >> 5;
    if (lane == 0) wsum[wid] = contrib;
    __syncthreads();
    if (wid == 0) {
        int v2 = (lane < 12) ? wsum[lane] : 0;
        #pragma unroll
        for (int o = 8; o > 0; o >>= 1)
            v2 += __shfl_down_sync(0xFFFFFFFFu, v2, o);
        if (lane == 0) atomicAdd(&g_border, (unsigned int)v2);
    }
}

// ---------------------------------------------------------------------------
// Kernel 4: combine.
// ---------------------------------------------------------------------------
__global__ void final_kernel(float* out) {
    out[0] = g_ce + 0.2f * (float)g_border;
}

extern "C" void kernel_launch(void* const* d_in, const int* in_sizes, int n_in,
                              void* d_out, int out_size) {
    const float* slices  = (const float*)d_in[0];
    const int*   targets = (const int*)d_in[1];   // JAX int64 -> int32 (x64 disabled)
    float* out = (float*)d_out;

    init_kernel<<<1, 1>>>();
    ce_argmax_kernel<<<NPIX / 256, 256>>>(slices, targets);
    vert_dt_kernel<<<dim3(Wn / 128, Bn), 128>>>(targets);
    horiz_dt_kernel<<<Bn * Hn, Wn>>>();
    final_kernel<<<1, 1>>>(out);
}